// round 1
// baseline (speedup 1.0000x reference)
#include <cuda_runtime.h>
#include <math.h>
#include <stdint.h>

#define M_TOT 16384
#define D_IN  2048
#define N_TOT 1728
#define SEQ   4096

// column offsets inside a packed Y row
#define OFF_AQ 0
#define OFF_AK 128
#define OFF_AV 160
#define OFF_BQ 192
#define OFF_BK 1216
#define OFF_BV 1472

// scratch (static device arrays: allocation-free per harness rules)
__device__ float g_X[(size_t)M_TOT * D_IN];     // tf32-rounded X
__device__ float g_W[(size_t)D_IN * N_TOT];     // tf32-rounded packed W
__device__ float g_Y[(size_t)M_TOT * N_TOT];    // GEMM result
__device__ float g_cos[SEQ * 64];
__device__ float g_sin[SEQ * 64];

__device__ __forceinline__ float to_tf32(float x) {
    uint32_t r;
    asm("cvt.rna.tf32.f32 %0, %1;" : "=r"(r) : "f"(x));
    return __uint_as_float(r);
}

__global__ __launch_bounds__(256) void k_prep_x(const float* __restrict__ x) {
    int i = blockIdx.x * 256 + threadIdx.x;
    if (i < M_TOT * D_IN) g_X[i] = to_tf32(x[i]);
}

__global__ __launch_bounds__(256) void k_prep_w(
    const float* __restrict__ wa_q, const float* __restrict__ wa_k,
    const float* __restrict__ wa_v, const float* __restrict__ wb_q,
    const float* __restrict__ wb_k, const float* __restrict__ wb_v) {
    int i = blockIdx.x * 256 + threadIdx.x;
    if (i >= D_IN * N_TOT) return;
    int k = i / N_TOT;
    int n = i - k * N_TOT;
    float v;
    if      (n < 128)  v = wa_q[k * 128  + n];
    else if (n < 160)  v = wa_k[k * 32   + (n - 128)];
    else if (n < 192)  v = wa_v[k * 32   + (n - 160)];
    else if (n < 1216) v = wb_q[k * 1024 + (n - 192)];
    else if (n < 1472) v = wb_k[k * 256  + (n - 1216)];
    else               v = wb_v[k * 256  + (n - 1472)];
    g_W[i] = to_tf32(v);
}

__global__ __launch_bounds__(256) void k_rope() {
    int i = blockIdx.x * 256 + threadIdx.x;
    if (i >= SEQ * 64) return;
    int s = i >> 6, d = i & 63;
    // inv_freq = 10000^(-d/64); mirror reference's fp32 quantization of t*inv_freq
    float ex   = -(float)d * (1.0f / 64.0f);
    float invf = exp2f(ex * 13.28771237954945f); // log2(10000)
    float f    = (float)s * invf;                 // fp32 product, like jnp.outer(f32)
    float sn, cs;
    sincosf(f, &sn, &cs);
    g_cos[i] = cs;
    g_sin[i] = sn;
}

// ---------------- GEMM: Y = X @ W, tf32 mma.sync, cp.async double-buffer ---
#define BM 128
#define BN 64
#define BK 32

__device__ __forceinline__ void cp16(float* smem, const float* g) {
    uint32_t s = (uint32_t)__cvta_generic_to_shared(smem);
    asm volatile("cp.async.cg.shared.global [%0], [%1], 16;" :: "r"(s), "l"(g));
}

__global__ __launch_bounds__(256, 2) void k_gemm() {
    __shared__ float sA[2][BM * BK];   // XOR-swizzled [r][c]: idx = r*32 + (c ^ ((r&7)<<2))
    __shared__ float sB[2][BK * BN];   // XOR-swizzled [k][n]: idx = k*64 + (n ^ ((k&3)<<3))
    const int tid  = threadIdx.x;
    const int bn   = blockIdx.x, bm = blockIdx.y;
    const int lane = tid & 31, wid = tid >> 5;
    const int wm = (wid & 3) << 5;   // warp row base: 0..96
    const int wn = (wid >> 2) << 5;  // warp col base: 0 or 32
    const int gp = lane >> 2, u = lane & 3;

    float acc[2][4][4];
#pragma unroll
    for (int a = 0; a < 2; a++)
#pragma unroll
        for (int b = 0; b < 4; b++)
#pragma unroll
            for (int c = 0; c < 4; c++) acc[a][b][c] = 0.f;

    auto load_tiles = [&](int st, int kt) {
#pragma unroll
        for (int j = 0; j < 4; j++) {          // A: 128x32 fp32 = 1024 16B chunks
            int chunk = tid + j * 256;
            int r  = chunk >> 3;
            int c4 = (chunk & 7) << 2;
            cp16(&sA[st][r * 32 + (c4 ^ ((r & 7) << 2))],
                 g_X + (size_t)(bm * 128 + r) * D_IN + kt * 32 + c4);
        }
#pragma unroll
        for (int j = 0; j < 2; j++) {          // B: 32x64 fp32 = 512 16B chunks
            int chunk = tid + j * 256;
            int r  = chunk >> 4;
            int c4 = (chunk & 15) << 2;
            cp16(&sB[st][r * 64 + (c4 ^ ((r & 3) << 3))],
                 g_W + (size_t)(kt * 32 + r) * N_TOT + bn * 64 + c4);
        }
    };

    load_tiles(0, 0);
    asm volatile("cp.async.commit_group;");

    for (int kt = 0; kt < D_IN / BK; kt++) {
        const int st = kt & 1;
        if (kt + 1 < D_IN / BK) {
            load_tiles(st ^ 1, kt + 1);
            asm volatile("cp.async.commit_group;");
            asm volatile("cp.async.wait_group 1;");
        } else {
            asm volatile("cp.async.wait_group 0;");
        }
        __syncthreads();

        const float* A  = sA[st];
        const float* Bs = sB[st];
#pragma unroll
        for (int ks = 0; ks < 4; ks++) {
            uint32_t afr[2][4], bfr[4][2];
            const int c0 = ks * 8 + u;
#pragma unroll
            for (int tm = 0; tm < 2; tm++) {
                int r0 = wm + tm * 16 + gp;
                int r1 = r0 + 8;
                int s0 = (r0 & 7) << 2;
                int s1 = (r1 & 7) << 2;
                afr[tm][0] = __float_as_uint(A[r0 * 32 + (c0 ^ s0)]);
                afr[tm][1] = __float_as_uint(A[r1 * 32 + (c0 ^ s1)]);
                afr[tm][2] = __float_as_uint(A[r0 * 32 + ((c0 + 4) ^ s0)]);
                afr[tm][3] = __float_as_uint(A[r1 * 32 + ((c0 + 4) ^ s1)]);
            }
#pragma unroll
            for (int tn = 0; tn < 4; tn++) {
                int n  = wn + tn * 8 + gp;
                int k0 = ks * 8 + u;
                int sw = (k0 & 3) << 3;
                bfr[tn][0] = __float_as_uint(Bs[k0 * 64 + (n ^ sw)]);
                bfr[tn][1] = __float_as_uint(Bs[(k0 + 4) * 64 + (n ^ sw)]);
            }
#pragma unroll
            for (int tm = 0; tm < 2; tm++)
#pragma unroll
                for (int tn = 0; tn < 4; tn++) {
                    float* c = acc[tm][tn];
                    asm volatile(
                        "mma.sync.aligned.m16n8k8.row.col.f32.tf32.tf32.f32 "
                        "{%0,%1,%2,%3}, {%4,%5,%6,%7}, {%8,%9}, {%0,%1,%2,%3};"
                        : "+f"(c[0]), "+f"(c[1]), "+f"(c[2]), "+f"(c[3])
                        : "r"(afr[tm][0]), "r"(afr[tm][1]), "r"(afr[tm][2]), "r"(afr[tm][3]),
                          "r"(bfr[tn][0]), "r"(bfr[tn][1]));
                }
        }
        __syncthreads();
    }

#pragma unroll
    for (int tm = 0; tm < 2; tm++) {
        int row0 = bm * 128 + wm + tm * 16 + gp;
#pragma unroll
        for (int tn = 0; tn < 4; tn++) {
            int col = bn * 64 + wn + tn * 8 + 2 * u;
            *reinterpret_cast<float2*>(&g_Y[(size_t)row0 * N_TOT + col]) =
                make_float2(acc[tm][tn][0], acc[tm][tn][1]);
            *reinterpret_cast<float2*>(&g_Y[(size_t)(row0 + 8) * N_TOT + col]) =
                make_float2(acc[tm][tn][2], acc[tm][tn][3]);
        }
    }
}

// ---------------- epilogue: rope + rank contraction -----------------------
__global__ __launch_bounds__(256) void k_epi(float* __restrict__ out, int third) {
    const int t = blockIdx.x;          // token id 0..16383
    const int s = t & (SEQ - 1);       // position in sequence
    __shared__ float sY[N_TOT];
    __shared__ float sBq[1024];
    __shared__ float sBk[256];
    const int tid = threadIdx.x;
    const float* Yr = g_Y + (size_t)t * N_TOT;
    for (int i = tid; i < N_TOT; i += 256) sY[i] = Yr[i];
    __syncthreads();

    // rope on B_q (8 x 128) : 512 half-pairs
    for (int p = tid; p < 512; p += 256) {
        int r = p >> 6, d = p & 63;
        float cs = g_cos[(s << 6) + d], sn = g_sin[(s << 6) + d];
        float x1 = sY[OFF_BQ + r * 128 + d];
        float x2 = sY[OFF_BQ + r * 128 + 64 + d];
        sBq[r * 128 + d]      = x1 * cs + x2 * sn;
        sBq[r * 128 + 64 + d] = x2 * cs - x1 * sn;
    }
    // rope on B_k (2 x 128) : 128 half-pairs
    if (tid < 128) {
        int r = tid >> 6, d = tid & 63;
        float cs = g_cos[(s << 6) + d], sn = g_sin[(s << 6) + d];
        float x1 = sY[OFF_BK + r * 128 + d];
        float x2 = sY[OFF_BK + r * 128 + 64 + d];
        sBk[r * 128 + d]      = x1 * cs + x2 * sn;
        sBk[r * 128 + 64 + d] = x2 * cs - x1 * sn;
    }
    __syncthreads();

    const int d  = tid & 127;
    const int h0 = tid >> 7;
    float* oq = out;
    float* ok = out + (size_t)third;
    float* ov = out + (size_t)2 * third;
    const size_t base = (size_t)t * 2048 + d;
#pragma unroll
    for (int h = h0; h < 16; h += 2) {
        float q = 0.f;
#pragma unroll
        for (int r = 0; r < 8; r++) q += sY[OFF_AQ + h * 8 + r] * sBq[r * 128 + d];
        oq[base + h * 128] = q * 0.125f;
        float kk = sY[OFF_AK + h * 2] * sBk[d] + sY[OFF_AK + h * 2 + 1] * sBk[128 + d];
        ok[base + h * 128] = kk * 0.5f;
        float vv = sY[OFF_AV + h * 2] * sY[OFF_BV + d]
                 + sY[OFF_AV + h * 2 + 1] * sY[OFF_BV + 128 + d];
        ov[base + h * 128] = vv * 0.5f;
    }
}

extern "C" void kernel_launch(void* const* d_in, const int* in_sizes, int n_in,
                              void* d_out, int out_size) {
    const float* x    = (const float*)d_in[0];
    const float* wa_q = (const float*)d_in[1];
    const float* wa_k = (const float*)d_in[2];
    const float* wa_v = (const float*)d_in[3];
    const float* wb_q = (const float*)d_in[4];
    const float* wb_k = (const float*)d_in[5];
    const float* wb_v = (const float*)d_in[6];

    k_prep_x<<<(M_TOT * D_IN + 255) / 256, 256>>>(x);
    k_prep_w<<<(D_IN * N_TOT + 255) / 256, 256>>>(wa_q, wa_k, wa_v, wb_q, wb_k, wb_v);
    k_rope<<<(SEQ * 64 + 255) / 256, 256>>>();
    dim3 grid(N_TOT / BN, M_TOT / BM);
    k_gemm<<<grid, 256>>>();
    k_epi<<<M_TOT, 256>>>((float*)d_out, out_size / 3);
}